// round 8
// baseline (speedup 1.0000x reference)
#include <cuda_runtime.h>
#include <cuda_fp16.h>

// Problem constants
#define BATCH    8
#define S_BYTES  8192
#define NUM_EMB  384
#define BYTE_DIM 128
#define EMB_DIM  1024
#define NUM_TOK  2048
#define SCALE_F  11.313708498984761f  // sqrt(128)

// proj = SCALE * emb @ W^T, stored fp16: [NUM_EMB, EMB_DIM] (768 KB, L2-resident)
__device__ __half g_proj_h[NUM_EMB * EMB_DIM];
// Segment starts: g_start[b][t] = first byte index s with byte_groups[b][s] >= t
__device__ int g_start[BATCH][NUM_TOK + 1];

// ---------------------------------------------------------------------------
// Kernel 1 (fused): blocks [0,384) tiny GEMM proj = SCALE*emb@W^T (fp32 math,
// fp16 store), blocks [384,640) segment boundaries from sorted byte_groups.
// ---------------------------------------------------------------------------
#define BM 32
#define BN 32
#define SPITCH 33
#define GEMM_BLOCKS 384
#define SEG_BLOCKS  256

__global__ __launch_bounds__(256) void prep_kernel(const float* __restrict__ emb,
                                                   const float* __restrict__ W,
                                                   const int* __restrict__ bg) {
    const int tid = threadIdx.x;

    if (blockIdx.x >= GEMM_BLOCKS) {
        // ---- segment boundaries ----
        const int blkk = blockIdx.x - GEMM_BLOCKS;
        const int b    = blkk >> 5;
        const int s    = (blkk & 31) * 256 + tid;
        const int* __restrict__ row = bg + (size_t)b * S_BYTES;

        const int g  = row[s];
        const int gp = (s == 0) ? -1 : row[s - 1];
        for (int t = gp + 1; t <= g; ++t) g_start[b][t] = s;
        if (s == S_BYTES - 1) {
            for (int t = g + 1; t <= NUM_TOK; ++t) g_start[b][t] = S_BYTES;
        }
        return;
    }

    // ---- tiny GEMM: 32x32 tile, full K in smem, one sync ----
    __shared__ float As[BYTE_DIM][SPITCH];  // [k][m]
    __shared__ float Ws[BYTE_DIM][SPITCH];  // [k][n]

    const int bn = blockIdx.x & 31;
    const int bm = blockIdx.x >> 5;
    const int tx = tid & 15;
    const int ty = tid >> 4;
    const int m0 = ty * 2;
    const int n0 = tx * 2;

    const float* __restrict__ A  = emb + (size_t)(bm * BM) * BYTE_DIM;
    const float* __restrict__ Wt = W   + (size_t)(bn * BN) * BYTE_DIM;

    #pragma unroll
    for (int i = 0; i < 16; ++i) {
        int f = tid + i * 256;
        int k = f & 127;
        int r = f >> 7;
        As[k][r] = A [(size_t)r * BYTE_DIM + k];
        Ws[k][r] = Wt[(size_t)r * BYTE_DIM + k];
    }
    __syncthreads();

    float acc[2][2] = {};
    #pragma unroll 8
    for (int k = 0; k < BYTE_DIM; ++k) {
        float a0 = As[k][m0], a1 = As[k][m0 + 1];
        float w0 = Ws[k][n0], w1 = Ws[k][n0 + 1];
        acc[0][0] = fmaf(a0, w0, acc[0][0]);
        acc[0][1] = fmaf(a0, w1, acc[0][1]);
        acc[1][0] = fmaf(a1, w0, acc[1][0]);
        acc[1][1] = fmaf(a1, w1, acc[1][1]);
    }

    #pragma unroll
    for (int i = 0; i < 2; ++i) {
        __half2 h = __floats2half2_rn(acc[i][0] * SCALE_F, acc[i][1] * SCALE_F);
        *reinterpret_cast<__half2*>(
            g_proj_h + (size_t)(bm * BM + m0 + i) * EMB_DIM + bn * BN + n0) = h;
    }
}

// ---------------------------------------------------------------------------
// Kernel 2: ragged mean over fp16 proj rows.
// Two warps per token (512 channels each). 512 THREADS = 16 warps = 8 tokens
// per block (round 7 bug: this was launched with 256 threads, leaving half
// the tokens unwritten). Segment byte-ids are prefetched cooperatively (one
// coalesced LDG per <=32 bytes) and broadcast via shfl, so gather LDGs never
// wait on a dependent index load and pipeline back-to-back into L2.
// grid = (NUM_TOK/8, BATCH).
// ---------------------------------------------------------------------------
#define POOL_THREADS 512

__global__ __launch_bounds__(POOL_THREADS) void pool_kernel(const int* __restrict__ x,
                                                            float* __restrict__ out) {
    const int b    = blockIdx.y;
    const int wid  = threadIdx.x >> 5;     // 0..15
    const int lane = threadIdx.x & 31;
    const int t    = blockIdx.x * 8 + (wid >> 1);
    const int hf   = wid & 1;              // which 512-channel half

    const int s0 = g_start[b][t];
    const int s1 = g_start[b][t + 1];
    const int cnt = s1 - s0;

    const int* __restrict__ xr = x + (size_t)b * S_BYTES;
    // proj row = 256 uint2 (4 halves each); this warp's half starts at +128.
    const uint2* __restrict__ p =
        reinterpret_cast<const uint2*>(g_proj_h) + hf * 128;

    float4 acc[4];
    #pragma unroll
    for (int j = 0; j < 4; ++j) acc[j] = make_float4(0.f, 0.f, 0.f, 0.f);

    for (int base = s0; base < s1; base += 32) {
        const int n = min(32, s1 - base);
        int myx = 0;
        if (base + lane < s1) myx = xr[base + lane];  // one coalesced load

        for (int i = 0; i < n; ++i) {
            const int e = __shfl_sync(0xffffffffu, myx, i);  // no mem dep
            const uint2* __restrict__ pr = p + (size_t)e * (EMB_DIM / 4);
            #pragma unroll
            for (int j = 0; j < 4; ++j) {
                uint2 u = pr[lane + 32 * j];  // coalesced 256B wavefront, L2-hit
                __half2 h0 = *reinterpret_cast<__half2*>(&u.x);
                __half2 h1 = *reinterpret_cast<__half2*>(&u.y);
                float2 f0 = __half22float2(h0);
                float2 f1 = __half22float2(h1);
                acc[j].x += f0.x; acc[j].y += f0.y;
                acc[j].z += f1.x; acc[j].w += f1.y;
            }
        }
    }

    const float inv = 1.0f / (float)(cnt > 0 ? cnt : 1);

    float4* __restrict__ o = reinterpret_cast<float4*>(out) +
        (((size_t)b * NUM_TOK) + t) * (EMB_DIM / 4) + hf * 128;
    #pragma unroll
    for (int j = 0; j < 4; ++j) {
        float4 v = make_float4(acc[j].x * inv, acc[j].y * inv,
                               acc[j].z * inv, acc[j].w * inv);
        o[lane + 32 * j] = v;  // coalesced STG.128
    }
}

// ---------------------------------------------------------------------------
// Launch
// ---------------------------------------------------------------------------
extern "C" void kernel_launch(void* const* d_in, const int* in_sizes, int n_in,
                              void* d_out, int out_size) {
    const int*   x    = (const int*)  d_in[0];  // [B, S_BYTES] int32
    const int*   bg   = (const int*)  d_in[1];  // [B, S_BYTES] int32 (sorted per row)
    const float* emb  = (const float*)d_in[2];  // [NUM_EMB, BYTE_DIM] fp32
    const float* wout = (const float*)d_in[3];  // [EMB_DIM, BYTE_DIM] fp32
    float* out = (float*)d_out;                 // [B, NUM_TOK, EMB_DIM] fp32

    (void)in_sizes; (void)n_in; (void)out_size;

    prep_kernel<<<GEMM_BLOCKS + SEG_BLOCKS, 256>>>(emb, wout, bg);

    dim3 pgrid(NUM_TOK / 8, BATCH);             // (256, 8) = 2048 blocks
    pool_kernel<<<pgrid, POOL_THREADS>>>(x, out);
}

// round 9
// speedup vs baseline: 1.0077x; 1.0077x over previous
#include <cuda_runtime.h>
#include <cuda_fp16.h>

// Problem constants
#define BATCH    8
#define S_BYTES  8192
#define NUM_EMB  384
#define BYTE_DIM 128
#define EMB_DIM  1024
#define NUM_TOK  2048
#define SCALE_F  11.313708498984761f  // sqrt(128)

// proj = SCALE * emb @ W^T, stored fp16: [NUM_EMB, EMB_DIM] (768 KB, L2-resident)
__device__ __half g_proj_h[NUM_EMB * EMB_DIM];
// Segment starts: g_start[b][t] = first byte index s with byte_groups[b][s] >= t
__device__ int g_start[BATCH][NUM_TOK + 1];

// ---------------------------------------------------------------------------
// Kernel 1 (fused): blocks [0,384) tiny GEMM proj = SCALE*emb@W^T (fp32 math,
// fp16 store), blocks [384,640) segment boundaries from sorted byte_groups.
// ---------------------------------------------------------------------------
#define BM 32
#define BN 32
#define SPITCH 33
#define GEMM_BLOCKS 384
#define SEG_BLOCKS  256

__global__ __launch_bounds__(256) void prep_kernel(const float* __restrict__ emb,
                                                   const float* __restrict__ W,
                                                   const int* __restrict__ bg) {
    const int tid = threadIdx.x;

    if (blockIdx.x >= GEMM_BLOCKS) {
        // ---- segment boundaries ----
        const int blkk = blockIdx.x - GEMM_BLOCKS;
        const int b    = blkk >> 5;
        const int s    = (blkk & 31) * 256 + tid;
        const int* __restrict__ row = bg + (size_t)b * S_BYTES;

        const int g  = row[s];
        const int gp = (s == 0) ? -1 : row[s - 1];
        for (int t = gp + 1; t <= g; ++t) g_start[b][t] = s;
        if (s == S_BYTES - 1) {
            for (int t = g + 1; t <= NUM_TOK; ++t) g_start[b][t] = S_BYTES;
        }
        return;
    }

    // ---- tiny GEMM: 32x32 tile, full K in smem, one sync ----
    __shared__ float As[BYTE_DIM][SPITCH];  // [k][m]
    __shared__ float Ws[BYTE_DIM][SPITCH];  // [k][n]

    const int bn = blockIdx.x & 31;
    const int bm = blockIdx.x >> 5;
    const int tx = tid & 15;
    const int ty = tid >> 4;
    const int m0 = ty * 2;
    const int n0 = tx * 2;

    const float* __restrict__ A  = emb + (size_t)(bm * BM) * BYTE_DIM;
    const float* __restrict__ Wt = W   + (size_t)(bn * BN) * BYTE_DIM;

    #pragma unroll
    for (int i = 0; i < 16; ++i) {
        int f = tid + i * 256;
        int k = f & 127;
        int r = f >> 7;
        As[k][r] = A [(size_t)r * BYTE_DIM + k];
        Ws[k][r] = Wt[(size_t)r * BYTE_DIM + k];
    }
    __syncthreads();

    float acc[2][2] = {};
    #pragma unroll 8
    for (int k = 0; k < BYTE_DIM; ++k) {
        float a0 = As[k][m0], a1 = As[k][m0 + 1];
        float w0 = Ws[k][n0], w1 = Ws[k][n0 + 1];
        acc[0][0] = fmaf(a0, w0, acc[0][0]);
        acc[0][1] = fmaf(a0, w1, acc[0][1]);
        acc[1][0] = fmaf(a1, w0, acc[1][0]);
        acc[1][1] = fmaf(a1, w1, acc[1][1]);
    }

    #pragma unroll
    for (int i = 0; i < 2; ++i) {
        __half2 h = __floats2half2_rn(acc[i][0] * SCALE_F, acc[i][1] * SCALE_F);
        *reinterpret_cast<__half2*>(
            g_proj_h + (size_t)(bm * BM + m0 + i) * EMB_DIM + bn * BN + n0) = h;
    }
}

// ---------------------------------------------------------------------------
// Kernel 2: ragged mean over fp16 proj rows.
// Warp-per-token, FULL 1024 channels (best amortization: 4 KB payload per
// byte, 8 independent LDG.64). Byte indices prefetched 32-at-a-time with one
// coalesced LDG + shfl broadcast (no per-iteration dependent load), and the
// byte loop is unrolled by 2 -> 16 independent LDG.64 in flight per warp.
// grid = (NUM_TOK/8, BATCH), block = 256 (8 warps = 8 tokens).
// ---------------------------------------------------------------------------
__global__ __launch_bounds__(256) void pool_kernel(const int* __restrict__ x,
                                                   float* __restrict__ out) {
    const int b    = blockIdx.y;
    const int wid  = threadIdx.x >> 5;
    const int lane = threadIdx.x & 31;
    const int t    = blockIdx.x * 8 + wid;

    const int s0 = g_start[b][t];
    const int s1 = g_start[b][t + 1];
    const int cnt = s1 - s0;

    const int* __restrict__ xr = x + (size_t)b * S_BYTES;
    const uint2* __restrict__ p = reinterpret_cast<const uint2*>(g_proj_h);  // 256/row

    float4 acc[8];
    #pragma unroll
    for (int j = 0; j < 8; ++j) acc[j] = make_float4(0.f, 0.f, 0.f, 0.f);

    for (int base = s0; base < s1; base += 32) {
        const int nn = min(32, s1 - base);
        int myx = 0;
        if (base + lane < s1) myx = xr[base + lane];  // one coalesced load

        int i = 0;
        for (; i + 2 <= nn; i += 2) {
            const int e0 = __shfl_sync(0xffffffffu, myx, i);
            const int e1 = __shfl_sync(0xffffffffu, myx, i + 1);
            const uint2* __restrict__ p0 = p + (size_t)e0 * (EMB_DIM / 4);
            const uint2* __restrict__ p1 = p + (size_t)e1 * (EMB_DIM / 4);
            uint2 u0[8], u1[8];
            #pragma unroll
            for (int j = 0; j < 8; ++j) u0[j] = p0[lane + 32 * j];
            #pragma unroll
            for (int j = 0; j < 8; ++j) u1[j] = p1[lane + 32 * j];
            #pragma unroll
            for (int j = 0; j < 8; ++j) {
                float2 a0 = __half22float2(*reinterpret_cast<__half2*>(&u0[j].x));
                float2 a1 = __half22float2(*reinterpret_cast<__half2*>(&u0[j].y));
                float2 c0 = __half22float2(*reinterpret_cast<__half2*>(&u1[j].x));
                float2 c1 = __half22float2(*reinterpret_cast<__half2*>(&u1[j].y));
                acc[j].x += a0.x + c0.x; acc[j].y += a0.y + c0.y;
                acc[j].z += a1.x + c1.x; acc[j].w += a1.y + c1.y;
            }
        }
        if (i < nn) {
            const int e = __shfl_sync(0xffffffffu, myx, i);
            const uint2* __restrict__ pr = p + (size_t)e * (EMB_DIM / 4);
            uint2 u[8];
            #pragma unroll
            for (int j = 0; j < 8; ++j) u[j] = pr[lane + 32 * j];
            #pragma unroll
            for (int j = 0; j < 8; ++j) {
                float2 a0 = __half22float2(*reinterpret_cast<__half2*>(&u[j].x));
                float2 a1 = __half22float2(*reinterpret_cast<__half2*>(&u[j].y));
                acc[j].x += a0.x; acc[j].y += a0.y;
                acc[j].z += a1.x; acc[j].w += a1.y;
            }
        }
    }

    const float inv = 1.0f / (float)(cnt > 0 ? cnt : 1);

    float4* __restrict__ o =
        reinterpret_cast<float4*>(out) + (((size_t)b * NUM_TOK) + t) * (EMB_DIM / 4);
    #pragma unroll
    for (int j = 0; j < 8; ++j) {
        float4 v = make_float4(acc[j].x * inv, acc[j].y * inv,
                               acc[j].z * inv, acc[j].w * inv);
        o[lane + 32 * j] = v;  // coalesced STG.128
    }
}

// ---------------------------------------------------------------------------
// Launch
// ---------------------------------------------------------------------------
extern "C" void kernel_launch(void* const* d_in, const int* in_sizes, int n_in,
                              void* d_out, int out_size) {
    const int*   x    = (const int*)  d_in[0];  // [B, S_BYTES] int32
    const int*   bg   = (const int*)  d_in[1];  // [B, S_BYTES] int32 (sorted per row)
    const float* emb  = (const float*)d_in[2];  // [NUM_EMB, BYTE_DIM] fp32
    const float* wout = (const float*)d_in[3];  // [EMB_DIM, BYTE_DIM] fp32
    float* out = (float*)d_out;                 // [B, NUM_TOK, EMB_DIM] fp32

    (void)in_sizes; (void)n_in; (void)out_size;

    prep_kernel<<<GEMM_BLOCKS + SEG_BLOCKS, 256>>>(emb, wout, bg);

    dim3 pgrid(NUM_TOK / 8, BATCH);             // (256, 8) = 2048 blocks
    pool_kernel<<<pgrid, 256>>>(x, out);
}